// round 9
// baseline (speedup 1.0000x reference)
#include <cuda_runtime.h>
#include <cuda_fp16.h>
#include <cstdint>

// ---------------------------------------------------------------------------
// PatchCoreAnomalyHead: MLP tf32 mma.sync (512-thr CTAs); distance GEMM fp16
// m16n8k16 (512-thr CTAs). 4 warps/SMSP everywhere for latency hiding.
// ---------------------------------------------------------------------------

#define R_TOTAL 32768
#define C_IN    1024
#define C_HID   512
#define C_D     256
#define M_BANK  16384
#define NSPLIT  8

__device__ float  g_H[(size_t)R_TOTAL * C_HID];
__device__ float  g_P[(size_t)R_TOTAL * C_D];
__device__ __half g_P16[(size_t)R_TOTAL * C_D];
__device__ __half g_MB16[(size_t)M_BANK * C_D];
__device__ float  g_W1T[(size_t)C_HID * C_IN];
__device__ float  g_W2T[(size_t)C_D * C_HID];
__device__ float  g_m2[M_BANK];
__device__ float  g_x2[R_TOTAL];
__device__ float  g_pmin[NSPLIT * R_TOTAL];

// ---------------------------- helpers --------------------------------------
__device__ __forceinline__ uint32_t smem_u32(const void* p) {
    uint32_t a;
    asm("{ .reg .u64 t; cvta.to.shared.u64 t, %1; cvt.u32.u64 %0, t; }"
        : "=r"(a) : "l"(p));
    return a;
}
__device__ __forceinline__ void cp16(uint32_t dst, const void* src) {
    asm volatile("cp.async.cg.shared.global [%0], [%1], 16;" :: "r"(dst), "l"(src));
}
#define CP_COMMIT() asm volatile("cp.async.commit_group;" ::: "memory")
#define CP_WAIT0()  asm volatile("cp.async.wait_group 0;" ::: "memory")

__device__ __forceinline__ void mma_tf32(float (&d)[4],
                                         const uint32_t (&a)[4],
                                         const uint32_t (&b)[2]) {
    asm volatile(
        "mma.sync.aligned.m16n8k8.row.col.f32.tf32.tf32.f32 "
        "{%0,%1,%2,%3}, {%4,%5,%6,%7}, {%8,%9}, {%0,%1,%2,%3};"
        : "+f"(d[0]), "+f"(d[1]), "+f"(d[2]), "+f"(d[3])
        : "r"(a[0]), "r"(a[1]), "r"(a[2]), "r"(a[3]), "r"(b[0]), "r"(b[1]));
}
__device__ __forceinline__ void mma_f16(float (&d)[4],
                                        const uint32_t (&a)[4],
                                        const uint32_t (&b)[2]) {
    asm volatile(
        "mma.sync.aligned.m16n8k16.row.col.f32.f16.f16.f32 "
        "{%0,%1,%2,%3}, {%4,%5,%6,%7}, {%8,%9}, {%0,%1,%2,%3};"
        : "+f"(d[0]), "+f"(d[1]), "+f"(d[2]), "+f"(d[3])
        : "r"(a[0]), "r"(a[1]), "r"(a[2]), "r"(a[3]), "r"(b[0]), "r"(b[1]));
}

// tf32 k=32 slab, warp tile 64x32 (4 m x 4 n). ALD,BLD ≡ 4 (mod 32).
template <int ALD, int BLD>
__device__ __forceinline__ void compute_k32n4(const float* __restrict__ aw,
                                              const float* __restrict__ bw,
                                              float (&acc)[4][4][4]) {
#pragma unroll
    for (int s = 0; s < 4; s++) {
        const int k0 = s * 8;
        uint32_t a[4][4], b[4][2];
#pragma unroll
        for (int mi = 0; mi < 4; mi++) {
            const uint32_t* p = (const uint32_t*)(aw + mi * 16 * ALD + k0);
            a[mi][0] = p[0];
            a[mi][1] = p[8 * ALD];
            a[mi][2] = p[4];
            a[mi][3] = p[8 * ALD + 4];
        }
#pragma unroll
        for (int ni = 0; ni < 4; ni++) {
            const uint32_t* p = (const uint32_t*)(bw + ni * 8 * BLD + k0);
            b[ni][0] = p[0];
            b[ni][1] = p[4];
        }
#pragma unroll
        for (int mi = 0; mi < 4; mi++)
#pragma unroll
            for (int ni = 0; ni < 4; ni++)
                mma_tf32(acc[mi][ni], a[mi], b[ni]);
    }
}

// fp16 k=64 slab, warp tile 64x32. (LD2/2) ≡ 4 (mod 32).
template <int ALD2, int BLD2>
__device__ __forceinline__ void compute_k64h32(const __half* __restrict__ aw,
                                               const __half* __restrict__ bw,
                                               float (&acc)[4][4][4]) {
#pragma unroll
    for (int s = 0; s < 4; s++) {
        const int k0 = s * 16;
        uint32_t a[4][4], b[4][2];
#pragma unroll
        for (int mi = 0; mi < 4; mi++) {
            const __half* p = aw + mi * 16 * ALD2 + k0;
            a[mi][0] = *(const uint32_t*)(p);
            a[mi][1] = *(const uint32_t*)(p + 8 * ALD2);
            a[mi][2] = *(const uint32_t*)(p + 8);
            a[mi][3] = *(const uint32_t*)(p + 8 * ALD2 + 8);
        }
#pragma unroll
        for (int ni = 0; ni < 4; ni++) {
            const __half* p = bw + ni * 8 * BLD2 + k0;
            b[ni][0] = *(const uint32_t*)(p);
            b[ni][1] = *(const uint32_t*)(p + 8);
        }
#pragma unroll
        for (int mi = 0; mi < 4; mi++)
#pragma unroll
            for (int ni = 0; ni < 4; ni++)
                mma_f16(acc[mi][ni], a[mi], b[ni]);
    }
}

// ------------------------- small prep kernels ------------------------------
__global__ void rowsq_kernel(const float* __restrict__ src, float* __restrict__ dst) {
    int i = blockIdx.x * blockDim.x + threadIdx.x;
    const float4* p = (const float4*)(src + (size_t)i * C_D);
    float s = 0.f;
#pragma unroll 8
    for (int q = 0; q < C_D / 4; q++) {
        float4 v = p[q];
        s += v.x * v.x + v.y * v.y + v.z * v.z + v.w * v.w;
    }
    dst[i] = s;
}
__global__ void conv_half_kernel(const float* __restrict__ src, __half* __restrict__ dst) {
    int i = blockIdx.x * blockDim.x + threadIdx.x;
    float4 v = ((const float4*)src)[i];
    __half2* d = (__half2*)(dst + (size_t)i * 4);
    d[0] = __floats2half2_rn(v.x, v.y);
    d[1] = __floats2half2_rn(v.z, v.w);
}
__global__ void transpose32(const float* __restrict__ src, float* __restrict__ dst,
                            int R, int C) {
    __shared__ float tile[32][33];
    int bx = blockIdx.x * 32, by = blockIdx.y * 32;
    int tx = threadIdx.x & 31, ty = threadIdx.x >> 5;
#pragma unroll
    for (int i = 0; i < 32; i += 8)
        tile[ty + i][tx] = src[(size_t)(by + ty + i) * C + bx + tx];
    __syncthreads();
#pragma unroll
    for (int i = 0; i < 32; i += 8)
        dst[(size_t)(bx + ty + i) * R + by + tx] = tile[tx][ty + i];
}

// ------------- MLP GEMM (tf32, 512 thr): Y = act(X @ WT^T + b) -------------
// CTA tile 256x128, 16 warps (4 row-bands x 4 col-bands), warp 64x32,
// k64 chunks double-buffered, one __syncthreads per chunk.
#define LDK64   68
#define MA_SZ   (256 * LDK64 * 4)          // 69632
#define MB_SZ   (128 * LDK64 * 4)          // 34816
#define MLP_SMEM (2 * (MA_SZ + MB_SZ))     // 208896

__global__ void __launch_bounds__(512)
mlp_tc(const float* __restrict__ X, const float* __restrict__ WT,
       const float* __restrict__ bias, float* __restrict__ Y,
       __half* __restrict__ Y16, int K, int N, int relu) {
    extern __shared__ char sm[];
    const uint32_t sbase = smem_u32(sm);
    const uint32_t Aoff[2] = {0u, MA_SZ};
    const uint32_t Boff[2] = {2 * MA_SZ, 2 * MA_SZ + MB_SZ};

    const int t = threadIdx.x, w = t >> 5, q = (t & 31) >> 2, c = t & 3;
    const int wr = w & 3, wc = w >> 2;             // 4 row x 4 col bands
    const int row0 = blockIdx.y * 256, col0 = blockIdx.x * 128;
    const int cr = t >> 4, c16 = (t & 15) * 4;     // 32 rows/pass, 16 f4/row

    float acc[4][4][4];
#pragma unroll
    for (int mi = 0; mi < 4; mi++)
#pragma unroll
        for (int ni = 0; ni < 4; ni++)
#pragma unroll
            for (int e = 0; e < 4; e++) acc[mi][ni][e] = 0.f;

    auto copy_chunk = [&](int j, int buf) {
#pragma unroll
        for (int i = 0; i < 8; i++) {              // A: 256 rows x 64 k
            int rr = cr + i * 32;
            cp16(sbase + Aoff[buf] + (uint32_t)(rr * LDK64 + c16) * 4,
                 X + (size_t)(row0 + rr) * K + j * 64 + c16);
        }
#pragma unroll
        for (int i = 0; i < 4; i++) {              // B: 128 rows x 64 k
            int rr = cr + i * 32;
            cp16(sbase + Boff[buf] + (uint32_t)(rr * LDK64 + c16) * 4,
                 WT + (size_t)(col0 + rr) * K + j * 64 + c16);
        }
    };

    const int nch = K / 64;
    copy_chunk(0, 0);
    CP_COMMIT();
    for (int j = 0; j < nch; j++) {
        CP_WAIT0();
        __syncthreads();
        if (j + 1 < nch) { copy_chunk(j + 1, (j + 1) & 1); CP_COMMIT(); }
        const float* ab = (const float*)(sm + Aoff[j & 1]);
        const float* bb = (const float*)(sm + Boff[j & 1]);
        const float* aw = ab + (wr * 64 + q) * LDK64 + c;
        const float* bw = bb + (wc * 32 + q) * LDK64 + c;
        compute_k32n4<LDK64, LDK64>(aw, bw, acc);
        compute_k32n4<LDK64, LDK64>(aw + 32, bw + 32, acc);
    }

#pragma unroll
    for (int mi = 0; mi < 4; mi++) {
        int rg = row0 + wr * 64 + mi * 16 + q;
#pragma unroll
        for (int ni = 0; ni < 4; ni++) {
            int cg = col0 + wc * 32 + ni * 8 + 2 * c;
            float2 bv = *(const float2*)(bias + cg);
            float v0 = acc[mi][ni][0] + bv.x;
            float v1 = acc[mi][ni][1] + bv.y;
            float v2 = acc[mi][ni][2] + bv.x;
            float v3 = acc[mi][ni][3] + bv.y;
            if (relu) {
                v0 = fmaxf(v0, 0.f); v1 = fmaxf(v1, 0.f);
                v2 = fmaxf(v2, 0.f); v3 = fmaxf(v3, 0.f);
            }
            *(float2*)&Y[(size_t)rg * N + cg] = make_float2(v0, v1);
            *(float2*)&Y[(size_t)(rg + 8) * N + cg] = make_float2(v2, v3);
            if (Y16) {
                *(__half2*)&Y16[(size_t)rg * N + cg] = __floats2half2_rn(v0, v1);
                *(__half2*)&Y16[(size_t)(rg + 8) * N + cg] = __floats2half2_rn(v2, v3);
            }
        }
    }
}

// ---------------- fused distance + partial min (fp16, 512 thr) -------------
// CTA = (bank eighth, 256 P-rows). 16 warps (4x4): warp tile 64x32.
#define ALD2    264                                // halfs; 264/2 ≡ 4 mod 32
#define BLD2    72                                 // halfs; 72/2  ≡ 4 mod 32
#define AH_SZ   (256 * ALD2 * 2)                   // 135168
#define BH_SZ   (128 * BLD2 * 2)                   // 18432
#define RED_OFF (AH_SZ + 2 * BH_SZ)                // 172032
#define DIST_SMEM (RED_OFF + 4 * 256 * 4)          // 176128

__global__ void __launch_bounds__(512)
dist_tc(const __half* __restrict__ P16, const __half* __restrict__ MB16) {
    extern __shared__ char sm[];
    const uint32_t sbase = smem_u32(sm);
    const __half* As = (const __half*)sm;
    const uint32_t Boff[2] = {AH_SZ, AH_SZ + BH_SZ};
    float* red = (float*)(sm + RED_OFF);

    const int t = threadIdx.x, w = t >> 5, q = (t & 31) >> 2, c = t & 3;
    const int wr = w & 3, wc = w >> 2;
    const int row0 = blockIdx.y * 256;
    const int qbase = blockIdx.x * (M_BANK / NSPLIT);

    // stationary P16 tile: 256 rows x 256 halfs
#pragma unroll
    for (int i = 0; i < 16; i++) {
        int f = t + i * 512;
        int rr = f >> 5, seg = f & 31;
        cp16(sbase + (uint32_t)(rr * ALD2 + seg * 8) * 2,
             P16 + (size_t)(row0 + rr) * C_D + seg * 8);
    }

    auto copy_chunk = [&](int jj, int buf) {
        int nt = jj >> 2, kc = jj & 3;
        int rr = t >> 2, seg = t & 3;
        const __half* src = MB16 + (size_t)(qbase + nt * 128 + rr) * C_D
                            + kc * 64 + seg * 16;
        uint32_t dst = sbase + Boff[buf] + (uint32_t)(rr * BLD2 + seg * 16) * 2;
        cp16(dst, src);
        cp16(dst + 16, src + 8);
    };

    float acc[4][4][4];
#pragma unroll
    for (int mi = 0; mi < 4; mi++)
#pragma unroll
        for (int ni = 0; ni < 4; ni++)
#pragma unroll
            for (int e = 0; e < 4; e++) acc[mi][ni][e] = 0.f;
    float runmin[4][2];
#pragma unroll
    for (int mi = 0; mi < 4; mi++) { runmin[mi][0] = 3.402823e38f; runmin[mi][1] = 3.402823e38f; }

    const __half* aw0 = As + (wr * 64 + q) * ALD2 + 2 * c;

    copy_chunk(0, 0);
    CP_COMMIT();
    const int NCH = (M_BANK / NSPLIT / 128) * 4;   // 64 chunks
    for (int jj = 0; jj < NCH; jj++) {
        CP_WAIT0();
        __syncthreads();
        if (jj + 1 < NCH) { copy_chunk(jj + 1, (jj + 1) & 1); CP_COMMIT(); }
        const int kc = jj & 3;
        const __half* bb = (const __half*)(sm + Boff[jj & 1]);
        compute_k64h32<ALD2, BLD2>(aw0 + kc * 64,
                                   bb + (wc * 32 + q) * BLD2 + 2 * c, acc);
        if (kc == 3) {
            const int nt = jj >> 2;
            const float* m2p = g_m2 + qbase + nt * 128 + wc * 32 + 2 * c;
#pragma unroll
            for (int mi = 0; mi < 4; mi++) {
                float m0 = runmin[mi][0], m1 = runmin[mi][1];
#pragma unroll
                for (int ni = 0; ni < 4; ni++) {
                    float2 m2v = *(const float2*)(m2p + ni * 8);
                    m0 = fminf(m0, fmaf(-2.f, acc[mi][ni][0], m2v.x));
                    m0 = fminf(m0, fmaf(-2.f, acc[mi][ni][1], m2v.y));
                    m1 = fminf(m1, fmaf(-2.f, acc[mi][ni][2], m2v.x));
                    m1 = fminf(m1, fmaf(-2.f, acc[mi][ni][3], m2v.y));
                    acc[mi][ni][0] = 0.f; acc[mi][ni][1] = 0.f;
                    acc[mi][ni][2] = 0.f; acc[mi][ni][3] = 0.f;
                }
                runmin[mi][0] = m0; runmin[mi][1] = m1;
            }
        }
    }

#pragma unroll
    for (int mi = 0; mi < 4; mi++)
#pragma unroll
        for (int s = 0; s < 2; s++) {
            float v = runmin[mi][s];
            v = fminf(v, __shfl_xor_sync(0xffffffffu, v, 1));
            v = fminf(v, __shfl_xor_sync(0xffffffffu, v, 2));
            if (c == 0) red[wc * 256 + wr * 64 + mi * 16 + s * 8 + q] = v;
        }
    __syncthreads();
    if (t < 256) {
        float m = fminf(fminf(red[t], red[256 + t]),
                        fminf(red[512 + t], red[768 + t]));
        g_pmin[(size_t)blockIdx.x * R_TOTAL + row0 + t] = m;
    }
}

// ------------------------------ combine ------------------------------------
__global__ void combine_kernel(float* __restrict__ out) {
    int r = blockIdx.x * blockDim.x + threadIdx.x;
    float m = 3.402823e38f;
#pragma unroll
    for (int s = 0; s < NSPLIT; s++)
        m = fminf(m, g_pmin[(size_t)s * R_TOTAL + r]);
    out[r] = sqrtf(fmaxf(g_x2[r] + m, 0.f));
}

// ---------------------------------------------------------------------------
extern "C" void kernel_launch(void* const* d_in, const int* in_sizes, int n_in,
                              void* d_out, int out_size) {
    (void)in_sizes; (void)n_in; (void)out_size;
    const float* features = (const float*)d_in[0];
    const float* W1       = (const float*)d_in[1];
    const float* b1       = (const float*)d_in[2];
    const float* W2       = (const float*)d_in[3];
    const float* b2       = (const float*)d_in[4];
    const float* MBp      = (const float*)d_in[5];
    float* out            = (float*)d_out;

    float *H, *Pp, *W1T, *W2T, *m2p, *x2p;
    __half *P16, *MB16;
    cudaGetSymbolAddress((void**)&H, g_H);
    cudaGetSymbolAddress((void**)&Pp, g_P);
    cudaGetSymbolAddress((void**)&P16, g_P16);
    cudaGetSymbolAddress((void**)&MB16, g_MB16);
    cudaGetSymbolAddress((void**)&W1T, g_W1T);
    cudaGetSymbolAddress((void**)&W2T, g_W2T);
    cudaGetSymbolAddress((void**)&m2p, g_m2);
    cudaGetSymbolAddress((void**)&x2p, g_x2);

    cudaFuncSetAttribute(mlp_tc, cudaFuncAttributeMaxDynamicSharedMemorySize, MLP_SMEM);
    cudaFuncSetAttribute(dist_tc, cudaFuncAttributeMaxDynamicSharedMemorySize, DIST_SMEM);

    transpose32<<<dim3(C_HID / 32, C_IN / 32), 256>>>(W1, W1T, C_IN, C_HID);
    transpose32<<<dim3(C_D / 32, C_HID / 32), 256>>>(W2, W2T, C_HID, C_D);
    rowsq_kernel<<<M_BANK / 256, 256>>>(MBp, m2p);
    conv_half_kernel<<<(M_BANK * C_D / 4) / 256, 256>>>(MBp, MB16);
    mlp_tc<<<dim3(C_HID / 128, R_TOTAL / 256), 512, MLP_SMEM>>>(
        features, W1T, b1, H, (__half*)nullptr, C_IN, C_HID, 1);
    mlp_tc<<<dim3(C_D / 128, R_TOTAL / 256), 512, MLP_SMEM>>>(
        H, W2T, b2, Pp, P16, C_HID, C_D, 0);
    rowsq_kernel<<<R_TOTAL / 256, 256>>>(Pp, x2p);
    dist_tc<<<dim3(NSPLIT, R_TOTAL / 256), 512, DIST_SMEM>>>(P16, MB16);
    combine_kernel<<<R_TOTAL / 256, 256>>>(out);
}

// round 12
// speedup vs baseline: 1.1159x; 1.1159x over previous
#include <cuda_runtime.h>
#include <cuda_fp16.h>
#include <cstdint>

// ---------------------------------------------------------------------------
// PatchCoreAnomalyHead: all-fp16 mma.sync m16n8k16 (fp32 accumulate).
// MLP fp16 (fp16 mantissa == tf32 mantissa for O(1-100) values); dist kernel
// is the proven R8 version unchanged.
// ---------------------------------------------------------------------------

#define R_TOTAL 32768
#define C_IN    1024
#define C_HID   512
#define C_D     256
#define M_BANK  16384
#define NSPLIT  8

__device__ __half g_X16[(size_t)R_TOTAL * C_IN];    // 64 MB
__device__ __half g_H16[(size_t)R_TOTAL * C_HID];   // 32 MB
__device__ __half g_P16[(size_t)R_TOTAL * C_D];     // 16 MB
__device__ __half g_MB16[(size_t)M_BANK * C_D];     // 8 MB
__device__ __half g_W1T[(size_t)C_HID * C_IN];
__device__ __half g_W2T[(size_t)C_D * C_HID];
__device__ float  g_m2[M_BANK];
__device__ float  g_x2[R_TOTAL];
__device__ float  g_pmin[NSPLIT * R_TOTAL];

// ---------------------------- helpers --------------------------------------
__device__ __forceinline__ uint32_t smem_u32(const void* p) {
    uint32_t a;
    asm("{ .reg .u64 t; cvta.to.shared.u64 t, %1; cvt.u32.u64 %0, t; }"
        : "=r"(a) : "l"(p));
    return a;
}
__device__ __forceinline__ void cp16(uint32_t dst, const void* src) {
    asm volatile("cp.async.cg.shared.global [%0], [%1], 16;" :: "r"(dst), "l"(src));
}
#define CP_COMMIT() asm volatile("cp.async.commit_group;" ::: "memory")
#define CP_WAIT0()  asm volatile("cp.async.wait_group 0;" ::: "memory")

__device__ __forceinline__ void mma_f16(float (&d)[4],
                                        const uint32_t (&a)[4],
                                        const uint32_t (&b)[2]) {
    asm volatile(
        "mma.sync.aligned.m16n8k16.row.col.f32.f16.f16.f32 "
        "{%0,%1,%2,%3}, {%4,%5,%6,%7}, {%8,%9}, {%0,%1,%2,%3};"
        : "+f"(d[0]), "+f"(d[1]), "+f"(d[2]), "+f"(d[3])
        : "r"(a[0]), "r"(a[1]), "r"(a[2]), "r"(a[3]), "r"(b[0]), "r"(b[1]));
}

// fp16 k=64 slab, warp tile 64x64 (MLP). (LD/2) ≡ 4 (mod 32): conflict-free.
template <int ALD2, int BLD2>
__device__ __forceinline__ void compute_k64h64(const __half* __restrict__ aw,
                                               const __half* __restrict__ bw,
                                               float (&acc)[4][8][4]) {
#pragma unroll
    for (int s = 0; s < 4; s++) {
        const int k0 = s * 16;
        uint32_t a[4][4], b[8][2];
#pragma unroll
        for (int mi = 0; mi < 4; mi++) {
            const __half* p = aw + mi * 16 * ALD2 + k0;
            a[mi][0] = *(const uint32_t*)(p);
            a[mi][1] = *(const uint32_t*)(p + 8 * ALD2);
            a[mi][2] = *(const uint32_t*)(p + 8);
            a[mi][3] = *(const uint32_t*)(p + 8 * ALD2 + 8);
        }
#pragma unroll
        for (int ni = 0; ni < 8; ni++) {
            const __half* p = bw + ni * 8 * BLD2 + k0;
            b[ni][0] = *(const uint32_t*)(p);
            b[ni][1] = *(const uint32_t*)(p + 8);
        }
#pragma unroll
        for (int mi = 0; mi < 4; mi++)
#pragma unroll
            for (int ni = 0; ni < 8; ni++)
                mma_f16(acc[mi][ni], a[mi], b[ni]);
    }
}

// fp16 k=64 slab, warp tile 64x32 (dist). (LD/2) ≡ 4 (mod 32): conflict-free.
template <int ALD2, int BLD2>
__device__ __forceinline__ void compute_k64h32(const __half* __restrict__ aw,
                                               const __half* __restrict__ bw,
                                               float (&acc)[4][4][4]) {
#pragma unroll
    for (int s = 0; s < 4; s++) {
        const int k0 = s * 16;
        uint32_t a[4][4], b[4][2];
#pragma unroll
        for (int mi = 0; mi < 4; mi++) {
            const __half* p = aw + mi * 16 * ALD2 + k0;
            a[mi][0] = *(const uint32_t*)(p);
            a[mi][1] = *(const uint32_t*)(p + 8 * ALD2);
            a[mi][2] = *(const uint32_t*)(p + 8);
            a[mi][3] = *(const uint32_t*)(p + 8 * ALD2 + 8);
        }
#pragma unroll
        for (int ni = 0; ni < 4; ni++) {
            const __half* p = bw + ni * 8 * BLD2 + k0;
            b[ni][0] = *(const uint32_t*)(p);
            b[ni][1] = *(const uint32_t*)(p + 8);
        }
#pragma unroll
        for (int mi = 0; mi < 4; mi++)
#pragma unroll
            for (int ni = 0; ni < 4; ni++)
                mma_f16(acc[mi][ni], a[mi], b[ni]);
    }
}

// ------------------------- small prep kernels ------------------------------
__global__ void rowsq_kernel(const float* __restrict__ src, float* __restrict__ dst) {
    int i = blockIdx.x * blockDim.x + threadIdx.x;
    const float4* p = (const float4*)(src + (size_t)i * C_D);
    float s = 0.f;
#pragma unroll 8
    for (int q = 0; q < C_D / 4; q++) {
        float4 v = p[q];
        s += v.x * v.x + v.y * v.y + v.z * v.z + v.w * v.w;
    }
    dst[i] = s;
}
// sum of squares of fp16 rows (matches dist's rounded P16 exactly)
__global__ void rowsq16_kernel(const __half* __restrict__ src, float* __restrict__ dst) {
    int i = blockIdx.x * blockDim.x + threadIdx.x;
    const __half2* p = (const __half2*)(src + (size_t)i * C_D);
    float s = 0.f;
#pragma unroll 16
    for (int q = 0; q < C_D / 2; q++) {
        float2 v = __half22float2(p[q]);
        s += v.x * v.x + v.y * v.y;
    }
    dst[i] = s;
}
__global__ void conv_half_kernel(const float* __restrict__ src, __half* __restrict__ dst) {
    int i = blockIdx.x * blockDim.x + threadIdx.x;
    float4 v = ((const float4*)src)[i];
    __half2* d = (__half2*)(dst + (size_t)i * 4);
    d[0] = __floats2half2_rn(v.x, v.y);
    d[1] = __floats2half2_rn(v.z, v.w);
}
// dst[C x R] (fp16) = src[R x C]^T
__global__ void transpose32h(const float* __restrict__ src, __half* __restrict__ dst,
                             int R, int C) {
    __shared__ float tile[32][33];
    int bx = blockIdx.x * 32, by = blockIdx.y * 32;
    int tx = threadIdx.x & 31, ty = threadIdx.x >> 5;
#pragma unroll
    for (int i = 0; i < 32; i += 8)
        tile[ty + i][tx] = src[(size_t)(by + ty + i) * C + bx + tx];
    __syncthreads();
#pragma unroll
    for (int i = 0; i < 32; i += 8)
        dst[(size_t)(bx + ty + i) * R + by + tx] = __float2half(tile[tx][ty + i]);
}

// ----------- MLP GEMM (fp16): Y16 = act(X16 @ WT16^T + bias) ---------------
// CTA 128x256, 8 warps (2 row x 4 col bands), warp 64x64, k128 chunks,
// cp.async double buffer, one __syncthreads per chunk.
#define MLDK    136                               // halfs; 136/2 ≡ 4 mod 32
#define MA_SZ   (128 * MLDK * 2)                  // 34816
#define MB_SZ   (256 * MLDK * 2)                  // 69632
#define MLP_SMEM (2 * (MA_SZ + MB_SZ))            // 208896

__global__ void __launch_bounds__(256)
mlp_h(const __half* __restrict__ X, const __half* __restrict__ WT,
      const float* __restrict__ bias, __half* __restrict__ Y16,
      int K, int N, int relu) {
    extern __shared__ char sm[];
    const uint32_t sbase = smem_u32(sm);
    const uint32_t Aoff[2] = {0u, MA_SZ};
    const uint32_t Boff[2] = {2 * MA_SZ, 2 * MA_SZ + MB_SZ};

    const int t = threadIdx.x, w = t >> 5, q = (t & 31) >> 2, c = t & 3;
    const int wr = w & 1, wc = w >> 1;
    const int row0 = blockIdx.y * 128, col0 = blockIdx.x * 256;
    const int cr = t >> 4, seg = (t & 15) * 16;    // 16 rows/pass, 16B segs

    float acc[4][8][4];
#pragma unroll
    for (int mi = 0; mi < 4; mi++)
#pragma unroll
        for (int ni = 0; ni < 8; ni++)
#pragma unroll
            for (int e = 0; e < 4; e++) acc[mi][ni][e] = 0.f;

    auto copy_chunk = [&](int j, int buf) {
#pragma unroll
        for (int i = 0; i < 8; i++) {              // A: 128 rows x 256 B
            int rr = cr + i * 16;
            cp16(sbase + Aoff[buf] + (uint32_t)(rr * MLDK) * 2 + seg,
                 (const char*)(X + (size_t)(row0 + rr) * K + j * 128) + seg);
        }
#pragma unroll
        for (int i = 0; i < 16; i++) {             // B: 256 rows x 256 B
            int rr = cr + i * 16;
            cp16(sbase + Boff[buf] + (uint32_t)(rr * MLDK) * 2 + seg,
                 (const char*)(WT + (size_t)(col0 + rr) * K + j * 128) + seg);
        }
    };

    const int nch = K / 128;
    copy_chunk(0, 0);
    CP_COMMIT();
    for (int j = 0; j < nch; j++) {
        CP_WAIT0();
        __syncthreads();
        if (j + 1 < nch) { copy_chunk(j + 1, (j + 1) & 1); CP_COMMIT(); }
        const __half* ab = (const __half*)(sm + Aoff[j & 1]);
        const __half* bb = (const __half*)(sm + Boff[j & 1]);
        const __half* aw = ab + (wr * 64 + q) * MLDK + 2 * c;
        const __half* bw = bb + (wc * 64 + q) * MLDK + 2 * c;
        compute_k64h64<MLDK, MLDK>(aw, bw, acc);
        compute_k64h64<MLDK, MLDK>(aw + 64, bw + 64, acc);
    }

#pragma unroll
    for (int mi = 0; mi < 4; mi++) {
        int rg = row0 + wr * 64 + mi * 16 + q;
#pragma unroll
        for (int ni = 0; ni < 8; ni++) {
            int cg = col0 + wc * 64 + ni * 8 + 2 * c;
            float2 bv = *(const float2*)(bias + cg);
            float v0 = acc[mi][ni][0] + bv.x;
            float v1 = acc[mi][ni][1] + bv.y;
            float v2 = acc[mi][ni][2] + bv.x;
            float v3 = acc[mi][ni][3] + bv.y;
            if (relu) {
                v0 = fmaxf(v0, 0.f); v1 = fmaxf(v1, 0.f);
                v2 = fmaxf(v2, 0.f); v3 = fmaxf(v3, 0.f);
            }
            *(__half2*)&Y16[(size_t)rg * N + cg] = __floats2half2_rn(v0, v1);
            *(__half2*)&Y16[(size_t)(rg + 8) * N + cg] = __floats2half2_rn(v2, v3);
        }
    }
}

// ---------------- fused distance + partial min (R8, unchanged) -------------
// CTA = (bank eighth, 256 P-rows). 16 warps (4x4): warp tile 64x32.
#define ALD2    264                                // halfs; 264/2 ≡ 4 mod 32
#define BLD2    72                                 // halfs; 72/2  ≡ 4 mod 32
#define AH_SZ   (256 * ALD2 * 2)                   // 135168
#define BH_SZ   (128 * BLD2 * 2)                   // 18432
#define RED_OFF (AH_SZ + 2 * BH_SZ)                // 172032
#define DIST_SMEM (RED_OFF + 4 * 256 * 4)          // 176128

__global__ void __launch_bounds__(512)
dist_tc(const __half* __restrict__ P16, const __half* __restrict__ MB16) {
    extern __shared__ char sm[];
    const uint32_t sbase = smem_u32(sm);
    const __half* As = (const __half*)sm;
    const uint32_t Boff[2] = {AH_SZ, AH_SZ + BH_SZ};
    float* red = (float*)(sm + RED_OFF);

    const int t = threadIdx.x, w = t >> 5, q = (t & 31) >> 2, c = t & 3;
    const int wr = w & 3, wc = w >> 2;
    const int row0 = blockIdx.y * 256;
    const int qbase = blockIdx.x * (M_BANK / NSPLIT);

    // stationary P16 tile: 256 rows x 256 halfs
#pragma unroll
    for (int i = 0; i < 16; i++) {
        int f = t + i * 512;
        int rr = f >> 5, seg = f & 31;
        cp16(sbase + (uint32_t)(rr * ALD2 + seg * 8) * 2,
             P16 + (size_t)(row0 + rr) * C_D + seg * 8);
    }

    auto copy_chunk = [&](int jj, int buf) {
        int nt = jj >> 2, kc = jj & 3;
        int rr = t >> 2, seg = t & 3;
        const __half* src = MB16 + (size_t)(qbase + nt * 128 + rr) * C_D
                            + kc * 64 + seg * 16;
        uint32_t dst = sbase + Boff[buf] + (uint32_t)(rr * BLD2 + seg * 16) * 2;
        cp16(dst, src);
        cp16(dst + 16, src + 8);
    };

    float acc[4][4][4];
#pragma unroll
    for (int mi = 0; mi < 4; mi++)
#pragma unroll
        for (int ni = 0; ni < 4; ni++)
#pragma unroll
            for (int e = 0; e < 4; e++) acc[mi][ni][e] = 0.f;
    float runmin[4][2];
#pragma unroll
    for (int mi = 0; mi < 4; mi++) { runmin[mi][0] = 3.402823e38f; runmin[mi][1] = 3.402823e38f; }

    const __half* aw0 = As + (wr * 64 + q) * ALD2 + 2 * c;

    copy_chunk(0, 0);
    CP_COMMIT();
    const int NCH = (M_BANK / NSPLIT / 128) * 4;   // 64 chunks
    for (int jj = 0; jj < NCH; jj++) {
        CP_WAIT0();
        __syncthreads();
        if (jj + 1 < NCH) { copy_chunk(jj + 1, (jj + 1) & 1); CP_COMMIT(); }
        const int kc = jj & 3;
        const __half* bb = (const __half*)(sm + Boff[jj & 1]);
        compute_k64h32<ALD2, BLD2>(aw0 + kc * 64,
                                   bb + (wc * 32 + q) * BLD2 + 2 * c, acc);
        if (kc == 3) {
            const int nt = jj >> 2;
            const float* m2p = g_m2 + qbase + nt * 128 + wc * 32 + 2 * c;
#pragma unroll
            for (int mi = 0; mi < 4; mi++) {
                float m0 = runmin[mi][0], m1 = runmin[mi][1];
#pragma unroll
                for (int ni = 0; ni < 4; ni++) {
                    float2 m2v = *(const float2*)(m2p + ni * 8);
                    m0 = fminf(m0, fmaf(-2.f, acc[mi][ni][0], m2v.x));
                    m0 = fminf(m0, fmaf(-2.f, acc[mi][ni][1], m2v.y));
                    m1 = fminf(m1, fmaf(-2.f, acc[mi][ni][2], m2v.x));
                    m1 = fminf(m1, fmaf(-2.f, acc[mi][ni][3], m2v.y));
                    acc[mi][ni][0] = 0.f; acc[mi][ni][1] = 0.f;
                    acc[mi][ni][2] = 0.f; acc[mi][ni][3] = 0.f;
                }
                runmin[mi][0] = m0; runmin[mi][1] = m1;
            }
        }
    }

#pragma unroll
    for (int mi = 0; mi < 4; mi++)
#pragma unroll
        for (int s = 0; s < 2; s++) {
            float v = runmin[mi][s];
            v = fminf(v, __shfl_xor_sync(0xffffffffu, v, 1));
            v = fminf(v, __shfl_xor_sync(0xffffffffu, v, 2));
            if (c == 0) red[wc * 256 + wr * 64 + mi * 16 + s * 8 + q] = v;
        }
    __syncthreads();
    if (t < 256) {
        float m = fminf(fminf(red[t], red[256 + t]),
                        fminf(red[512 + t], red[768 + t]));
        g_pmin[(size_t)blockIdx.x * R_TOTAL + row0 + t] = m;
    }
}

// ------------------------------ combine ------------------------------------
__global__ void combine_kernel(float* __restrict__ out) {
    int r = blockIdx.x * blockDim.x + threadIdx.x;
    float m = 3.402823e38f;
#pragma unroll
    for (int s = 0; s < NSPLIT; s++)
        m = fminf(m, g_pmin[(size_t)s * R_TOTAL + r]);
    out[r] = sqrtf(fmaxf(g_x2[r] + m, 0.f));
}

// ---------------------------------------------------------------------------
extern "C" void kernel_launch(void* const* d_in, const int* in_sizes, int n_in,
                              void* d_out, int out_size) {
    (void)in_sizes; (void)n_in; (void)out_size;
    const float* features = (const float*)d_in[0];
    const float* W1       = (const float*)d_in[1];
    const float* b1       = (const float*)d_in[2];
    const float* W2       = (const float*)d_in[3];
    const float* b2       = (const float*)d_in[4];
    const float* MBp      = (const float*)d_in[5];
    float* out            = (float*)d_out;

    float *m2p, *x2p;
    __half *X16, *H16, *P16, *MB16, *W1T, *W2T;
    cudaGetSymbolAddress((void**)&X16, g_X16);
    cudaGetSymbolAddress((void**)&H16, g_H16);
    cudaGetSymbolAddress((void**)&P16, g_P16);
    cudaGetSymbolAddress((void**)&MB16, g_MB16);
    cudaGetSymbolAddress((void**)&W1T, g_W1T);
    cudaGetSymbolAddress((void**)&W2T, g_W2T);
    cudaGetSymbolAddress((void**)&m2p, g_m2);
    cudaGetSymbolAddress((void**)&x2p, g_x2);

    cudaFuncSetAttribute(mlp_h, cudaFuncAttributeMaxDynamicSharedMemorySize, MLP_SMEM);
    cudaFuncSetAttribute(dist_tc, cudaFuncAttributeMaxDynamicSharedMemorySize, DIST_SMEM);

    transpose32h<<<dim3(C_HID / 32, C_IN / 32), 256>>>(W1, W1T, C_IN, C_HID);
    transpose32h<<<dim3(C_D / 32, C_HID / 32), 256>>>(W2, W2T, C_HID, C_D);
    rowsq_kernel<<<M_BANK / 256, 256>>>(MBp, m2p);
    conv_half_kernel<<<(M_BANK * C_D / 4) / 256, 256>>>(MBp, MB16);
    conv_half_kernel<<<(int)(((size_t)R_TOTAL * C_IN / 4) / 256), 256>>>(features, X16);
    mlp_h<<<dim3(C_HID / 256, R_TOTAL / 128), 256, MLP_SMEM>>>(
        X16, W1T, b1, H16, C_IN, C_HID, 1);
    mlp_h<<<dim3(C_D / 256, R_TOTAL / 128), 256, MLP_SMEM>>>(
        H16, W2T, b2, P16, C_HID, C_D, 0);
    rowsq16_kernel<<<R_TOTAL / 256, 256>>>(P16, x2p);
    dist_tc<<<dim3(NSPLIT, R_TOTAL / 256), 512, DIST_SMEM>>>(P16, MB16);
    combine_kernel<<<R_TOTAL / 256, 256>>>(out);
}

// round 13
// speedup vs baseline: 1.1222x; 1.0056x over previous
#include <cuda_runtime.h>
#include <cuda_fp16.h>
#include <cstdint>

// ---------------------------------------------------------------------------
// PatchCoreAnomalyHead: all-fp16 mma.sync m16n8k16 (fp32 accumulate).
// x^2 computed from rounded halfs -> fp16-consistent distances (rel_err 2e-5).
// ---------------------------------------------------------------------------

#define R_TOTAL 32768
#define C_IN    1024
#define C_HID   512
#define C_D     256
#define M_BANK  16384
#define NSPLIT  8

__device__ __half g_X16[(size_t)R_TOTAL * C_IN];    // 64 MB
__device__ __half g_H16[(size_t)R_TOTAL * C_HID];   // 32 MB
__device__ __half g_P16[(size_t)R_TOTAL * C_D];     // 16 MB
__device__ __half g_MB16[(size_t)M_BANK * C_D];     // 8 MB
__device__ __half g_W1T[(size_t)C_HID * C_IN];
__device__ __half g_W2T[(size_t)C_D * C_HID];
__device__ float  g_m2[M_BANK];
__device__ float  g_x2[R_TOTAL];
__device__ float  g_pmin[NSPLIT * R_TOTAL];

// ---------------------------- helpers --------------------------------------
__device__ __forceinline__ uint32_t smem_u32(const void* p) {
    uint32_t a;
    asm("{ .reg .u64 t; cvta.to.shared.u64 t, %1; cvt.u32.u64 %0, t; }"
        : "=r"(a) : "l"(p));
    return a;
}
__device__ __forceinline__ void cp16(uint32_t dst, const void* src) {
    asm volatile("cp.async.cg.shared.global [%0], [%1], 16;" :: "r"(dst), "l"(src));
}
#define CP_COMMIT() asm volatile("cp.async.commit_group;" ::: "memory")
#define CP_WAIT0()  asm volatile("cp.async.wait_group 0;" ::: "memory")

__device__ __forceinline__ void mma_f16(float (&d)[4],
                                        const uint32_t (&a)[4],
                                        const uint32_t (&b)[2]) {
    asm volatile(
        "mma.sync.aligned.m16n8k16.row.col.f32.f16.f16.f32 "
        "{%0,%1,%2,%3}, {%4,%5,%6,%7}, {%8,%9}, {%0,%1,%2,%3};"
        : "+f"(d[0]), "+f"(d[1]), "+f"(d[2]), "+f"(d[3])
        : "r"(a[0]), "r"(a[1]), "r"(a[2]), "r"(a[3]), "r"(b[0]), "r"(b[1]));
}

// fp16 k=64 slab, warp tile 64x64 (MLP). (LD/2) ≡ 4 (mod 32): conflict-free.
template <int ALD2, int BLD2>
__device__ __forceinline__ void compute_k64h64(const __half* __restrict__ aw,
                                               const __half* __restrict__ bw,
                                               float (&acc)[4][8][4]) {
#pragma unroll
    for (int s = 0; s < 4; s++) {
        const int k0 = s * 16;
        uint32_t a[4][4], b[8][2];
#pragma unroll
        for (int mi = 0; mi < 4; mi++) {
            const __half* p = aw + mi * 16 * ALD2 + k0;
            a[mi][0] = *(const uint32_t*)(p);
            a[mi][1] = *(const uint32_t*)(p + 8 * ALD2);
            a[mi][2] = *(const uint32_t*)(p + 8);
            a[mi][3] = *(const uint32_t*)(p + 8 * ALD2 + 8);
        }
#pragma unroll
        for (int ni = 0; ni < 8; ni++) {
            const __half* p = bw + ni * 8 * BLD2 + k0;
            b[ni][0] = *(const uint32_t*)(p);
            b[ni][1] = *(const uint32_t*)(p + 8);
        }
#pragma unroll
        for (int mi = 0; mi < 4; mi++)
#pragma unroll
            for (int ni = 0; ni < 8; ni++)
                mma_f16(acc[mi][ni], a[mi], b[ni]);
    }
}

// fp16 k=64 slab, warp tile 64x32 (dist). (LD/2) ≡ 4 (mod 32): conflict-free.
template <int ALD2, int BLD2>
__device__ __forceinline__ void compute_k64h32(const __half* __restrict__ aw,
                                               const __half* __restrict__ bw,
                                               float (&acc)[4][4][4]) {
#pragma unroll
    for (int s = 0; s < 4; s++) {
        const int k0 = s * 16;
        uint32_t a[4][4], b[4][2];
#pragma unroll
        for (int mi = 0; mi < 4; mi++) {
            const __half* p = aw + mi * 16 * ALD2 + k0;
            a[mi][0] = *(const uint32_t*)(p);
            a[mi][1] = *(const uint32_t*)(p + 8 * ALD2);
            a[mi][2] = *(const uint32_t*)(p + 8);
            a[mi][3] = *(const uint32_t*)(p + 8 * ALD2 + 8);
        }
#pragma unroll
        for (int ni = 0; ni < 4; ni++) {
            const __half* p = bw + ni * 8 * BLD2 + k0;
            b[ni][0] = *(const uint32_t*)(p);
            b[ni][1] = *(const uint32_t*)(p + 8);
        }
#pragma unroll
        for (int mi = 0; mi < 4; mi++)
#pragma unroll
            for (int ni = 0; ni < 4; ni++)
                mma_f16(acc[mi][ni], a[mi], b[ni]);
    }
}

// ------------------------- small prep kernels ------------------------------
__global__ void rowsq_kernel(const float* __restrict__ src, float* __restrict__ dst) {
    int i = blockIdx.x * blockDim.x + threadIdx.x;
    const float4* p = (const float4*)(src + (size_t)i * C_D);
    float s = 0.f;
#pragma unroll 8
    for (int q = 0; q < C_D / 4; q++) {
        float4 v = p[q];
        s += v.x * v.x + v.y * v.y + v.z * v.z + v.w * v.w;
    }
    dst[i] = s;
}
// sum of squares of fp16 rows (matches dist's rounded P16 exactly)
__global__ void rowsq16_kernel(const __half* __restrict__ src, float* __restrict__ dst) {
    int i = blockIdx.x * blockDim.x + threadIdx.x;
    const __half2* p = (const __half2*)(src + (size_t)i * C_D);
    float s = 0.f;
#pragma unroll 16
    for (int q = 0; q < C_D / 2; q++) {
        float2 v = __half22float2(p[q]);
        s += v.x * v.x + v.y * v.y;
    }
    dst[i] = s;
}
// fp32 -> fp16, 4 float4 per thread (MLP=4 to cover DRAM latency)
__global__ void conv_half_kernel(const float* __restrict__ src, __half* __restrict__ dst) {
    int base = blockIdx.x * 1024 + threadIdx.x;
#pragma unroll
    for (int k = 0; k < 4; k++) {
        int i = base + k * 256;
        float4 v = ((const float4*)src)[i];
        __half2* d = (__half2*)(dst + (size_t)i * 4);
        d[0] = __floats2half2_rn(v.x, v.y);
        d[1] = __floats2half2_rn(v.z, v.w);
    }
}
// dst[C x R] (fp16) = src[R x C]^T
__global__ void transpose32h(const float* __restrict__ src, __half* __restrict__ dst,
                             int R, int C) {
    __shared__ float tile[32][33];
    int bx = blockIdx.x * 32, by = blockIdx.y * 32;
    int tx = threadIdx.x & 31, ty = threadIdx.x >> 5;
#pragma unroll
    for (int i = 0; i < 32; i += 8)
        tile[ty + i][tx] = src[(size_t)(by + ty + i) * C + bx + tx];
    __syncthreads();
#pragma unroll
    for (int i = 0; i < 32; i += 8)
        dst[(size_t)(bx + ty + i) * R + by + tx] = __float2half(tile[tx][ty + i]);
}

// ----------- MLP GEMM (fp16): Y16 = act(X16 @ WT16^T + bias) ---------------
// CTA 128x256, 8 warps (2 row x 4 col bands), warp 64x64, k128 chunks,
// cp.async double buffer, one __syncthreads per chunk.
#define MLDK    136                               // halfs; 136/2 ≡ 4 mod 32
#define MA_SZ   (128 * MLDK * 2)                  // 34816
#define MB_SZ   (256 * MLDK * 2)                  // 69632
#define MLP_SMEM (2 * (MA_SZ + MB_SZ))            // 208896

__global__ void __launch_bounds__(256)
mlp_h(const __half* __restrict__ X, const __half* __restrict__ WT,
      const float* __restrict__ bias, __half* __restrict__ Y16,
      int K, int N, int relu) {
    extern __shared__ char sm[];
    const uint32_t sbase = smem_u32(sm);
    const uint32_t Aoff[2] = {0u, MA_SZ};
    const uint32_t Boff[2] = {2 * MA_SZ, 2 * MA_SZ + MB_SZ};

    const int t = threadIdx.x, w = t >> 5, q = (t & 31) >> 2, c = t & 3;
    const int wr = w & 1, wc = w >> 1;
    const int row0 = blockIdx.y * 128, col0 = blockIdx.x * 256;
    const int cr = t >> 4, seg = (t & 15) * 16;    // 16 rows/pass, 16B segs

    float acc[4][8][4];
#pragma unroll
    for (int mi = 0; mi < 4; mi++)
#pragma unroll
        for (int ni = 0; ni < 8; ni++)
#pragma unroll
            for (int e = 0; e < 4; e++) acc[mi][ni][e] = 0.f;

    auto copy_chunk = [&](int j, int buf) {
#pragma unroll
        for (int i = 0; i < 8; i++) {              // A: 128 rows x 256 B
            int rr = cr + i * 16;
            cp16(sbase + Aoff[buf] + (uint32_t)(rr * MLDK) * 2 + seg,
                 (const char*)(X + (size_t)(row0 + rr) * K + j * 128) + seg);
        }
#pragma unroll
        for (int i = 0; i < 16; i++) {             // B: 256 rows x 256 B
            int rr = cr + i * 16;
            cp16(sbase + Boff[buf] + (uint32_t)(rr * MLDK) * 2 + seg,
                 (const char*)(WT + (size_t)(col0 + rr) * K + j * 128) + seg);
        }
    };

    const int nch = K / 128;
    copy_chunk(0, 0);
    CP_COMMIT();
    for (int j = 0; j < nch; j++) {
        CP_WAIT0();
        __syncthreads();
        if (j + 1 < nch) { copy_chunk(j + 1, (j + 1) & 1); CP_COMMIT(); }
        const __half* ab = (const __half*)(sm + Aoff[j & 1]);
        const __half* bb = (const __half*)(sm + Boff[j & 1]);
        const __half* aw = ab + (wr * 64 + q) * MLDK + 2 * c;
        const __half* bw = bb + (wc * 64 + q) * MLDK + 2 * c;
        compute_k64h64<MLDK, MLDK>(aw, bw, acc);
        compute_k64h64<MLDK, MLDK>(aw + 64, bw + 64, acc);
    }

#pragma unroll
    for (int mi = 0; mi < 4; mi++) {
        int rg = row0 + wr * 64 + mi * 16 + q;
#pragma unroll
        for (int ni = 0; ni < 8; ni++) {
            int cg = col0 + wc * 64 + ni * 8 + 2 * c;
            float2 bv = *(const float2*)(bias + cg);
            float v0 = acc[mi][ni][0] + bv.x;
            float v1 = acc[mi][ni][1] + bv.y;
            float v2 = acc[mi][ni][2] + bv.x;
            float v3 = acc[mi][ni][3] + bv.y;
            if (relu) {
                v0 = fmaxf(v0, 0.f); v1 = fmaxf(v1, 0.f);
                v2 = fmaxf(v2, 0.f); v3 = fmaxf(v3, 0.f);
            }
            *(__half2*)&Y16[(size_t)rg * N + cg] = __floats2half2_rn(v0, v1);
            *(__half2*)&Y16[(size_t)(rg + 8) * N + cg] = __floats2half2_rn(v2, v3);
        }
    }
}

// ---------------- fused distance + partial min (fp16, 512 thr) -------------
// CTA = (bank eighth, 256 P-rows). 16 warps (4x4), warp tile 64x32,
// k128 chunks (2 x k64 compute), one __syncthreads per chunk.
#define ALD2    264                                // halfs; 264/2 ≡ 4 mod 32
#define BLDD    136                                // halfs; 136/2 ≡ 4 mod 32
#define AH_SZ   (256 * ALD2 * 2)                   // 135168
#define BH_SZ   (128 * BLDD * 2)                   // 34816
#define RED_OFF (AH_SZ + 2 * BH_SZ)                // 204800
#define DIST_SMEM (RED_OFF + 4 * 256 * 4)          // 208896

__global__ void __launch_bounds__(512)
dist_tc(const __half* __restrict__ P16, const __half* __restrict__ MB16) {
    extern __shared__ char sm[];
    const uint32_t sbase = smem_u32(sm);
    const __half* As = (const __half*)sm;
    const uint32_t Boff[2] = {AH_SZ, AH_SZ + BH_SZ};
    float* red = (float*)(sm + RED_OFF);

    const int t = threadIdx.x, w = t >> 5, q = (t & 31) >> 2, c = t & 3;
    const int wr = w & 3, wc = w >> 2;
    const int row0 = blockIdx.y * 256;
    const int qbase = blockIdx.x * (M_BANK / NSPLIT);

    // stationary P16 tile: 256 rows x 256 halfs
#pragma unroll
    for (int i = 0; i < 16; i++) {
        int f = t + i * 512;
        int rr = f >> 5, seg = f & 31;
        cp16(sbase + (uint32_t)(rr * ALD2 + seg * 8) * 2,
             P16 + (size_t)(row0 + rr) * C_D + seg * 8);
    }

    // per chunk: 128 bank rows x 128 halfs (256 B/row) -> 4 cp16 per thread
    auto copy_chunk = [&](int jj, int buf) {
        int nt = jj >> 1, kc = jj & 1;
        int rr = t >> 2, sq = (t & 3) * 64;        // 4 segs of 64B
        const char* src = (const char*)(MB16 + (size_t)(qbase + nt * 128 + rr) * C_D
                                        + kc * 128) + sq;
        uint32_t dst = sbase + Boff[buf] + (uint32_t)(rr * BLDD) * 2 + sq;
        cp16(dst, src);
        cp16(dst + 16, src + 16);
        cp16(dst + 32, src + 32);
        cp16(dst + 48, src + 48);
    };

    float acc[4][4][4];
#pragma unroll
    for (int mi = 0; mi < 4; mi++)
#pragma unroll
        for (int ni = 0; ni < 4; ni++)
#pragma unroll
            for (int e = 0; e < 4; e++) acc[mi][ni][e] = 0.f;
    float runmin[4][2];
#pragma unroll
    for (int mi = 0; mi < 4; mi++) { runmin[mi][0] = 3.402823e38f; runmin[mi][1] = 3.402823e38f; }

    const __half* aw0 = As + (wr * 64 + q) * ALD2 + 2 * c;

    copy_chunk(0, 0);
    CP_COMMIT();
    const int NCH = (M_BANK / NSPLIT / 128) * 2;   // 32 chunks (k128 each)
    for (int jj = 0; jj < NCH; jj++) {
        CP_WAIT0();
        __syncthreads();                            // covers As (jj=0) + reuse
        if (jj + 1 < NCH) { copy_chunk(jj + 1, (jj + 1) & 1); CP_COMMIT(); }
        const int kc = jj & 1;
        const __half* bb = (const __half*)(sm + Boff[jj & 1]);
        const __half* aw = aw0 + kc * 128;
        const __half* bw = bb + (wc * 32 + q) * BLDD + 2 * c;
        compute_k64h32<ALD2, BLDD>(aw, bw, acc);
        compute_k64h32<ALD2, BLDD>(aw + 64, bw + 64, acc);
        if (kc == 1) {
            const int nt = jj >> 1;
            const float* m2p = g_m2 + qbase + nt * 128 + wc * 32 + 2 * c;
#pragma unroll
            for (int mi = 0; mi < 4; mi++) {
                float m0 = runmin[mi][0], m1 = runmin[mi][1];
#pragma unroll
                for (int ni = 0; ni < 4; ni++) {
                    float2 m2v = *(const float2*)(m2p + ni * 8);
                    m0 = fminf(m0, fmaf(-2.f, acc[mi][ni][0], m2v.x));
                    m0 = fminf(m0, fmaf(-2.f, acc[mi][ni][1], m2v.y));
                    m1 = fminf(m1, fmaf(-2.f, acc[mi][ni][2], m2v.x));
                    m1 = fminf(m1, fmaf(-2.f, acc[mi][ni][3], m2v.y));
                    acc[mi][ni][0] = 0.f; acc[mi][ni][1] = 0.f;
                    acc[mi][ni][2] = 0.f; acc[mi][ni][3] = 0.f;
                }
                runmin[mi][0] = m0; runmin[mi][1] = m1;
            }
        }
    }

#pragma unroll
    for (int mi = 0; mi < 4; mi++)
#pragma unroll
        for (int s = 0; s < 2; s++) {
            float v = runmin[mi][s];
            v = fminf(v, __shfl_xor_sync(0xffffffffu, v, 1));
            v = fminf(v, __shfl_xor_sync(0xffffffffu, v, 2));
            if (c == 0) red[wc * 256 + wr * 64 + mi * 16 + s * 8 + q] = v;
        }
    __syncthreads();
    if (t < 256) {
        float m = fminf(fminf(red[t], red[256 + t]),
                        fminf(red[512 + t], red[768 + t]));
        g_pmin[(size_t)blockIdx.x * R_TOTAL + row0 + t] = m;
    }
}

// ------------------------------ combine ------------------------------------
__global__ void combine_kernel(float* __restrict__ out) {
    int r = blockIdx.x * blockDim.x + threadIdx.x;
    float m = 3.402823e38f;
#pragma unroll
    for (int s = 0; s < NSPLIT; s++)
        m = fminf(m, g_pmin[(size_t)s * R_TOTAL + r]);
    out[r] = sqrtf(fmaxf(g_x2[r] + m, 0.f));
}

// ---------------------------------------------------------------------------
extern "C" void kernel_launch(void* const* d_in, const int* in_sizes, int n_in,
                              void* d_out, int out_size) {
    (void)in_sizes; (void)n_in; (void)out_size;
    const float* features = (const float*)d_in[0];
    const float* W1       = (const float*)d_in[1];
    const float* b1       = (const float*)d_in[2];
    const float* W2       = (const float*)d_in[3];
    const float* b2       = (const float*)d_in[4];
    const float* MBp      = (const float*)d_in[5];
    float* out            = (float*)d_out;

    float *m2p, *x2p;
    __half *X16, *H16, *P16, *MB16, *W1T, *W2T;
    cudaGetSymbolAddress((void**)&X16, g_X16);
    cudaGetSymbolAddress((void**)&H16, g_H16);
    cudaGetSymbolAddress((void**)&P16, g_P16);
    cudaGetSymbolAddress((void**)&MB16, g_MB16);
    cudaGetSymbolAddress((void**)&W1T, g_W1T);
    cudaGetSymbolAddress((void**)&W2T, g_W2T);
    cudaGetSymbolAddress((void**)&m2p, g_m2);
    cudaGetSymbolAddress((void**)&x2p, g_x2);

    cudaFuncSetAttribute(mlp_h, cudaFuncAttributeMaxDynamicSharedMemorySize, MLP_SMEM);
    cudaFuncSetAttribute(dist_tc, cudaFuncAttributeMaxDynamicSharedMemorySize, DIST_SMEM);

    transpose32h<<<dim3(C_HID / 32, C_IN / 32), 256>>>(W1, W1T, C_IN, C_HID);
    transpose32h<<<dim3(C_D / 32, C_HID / 32), 256>>>(W2, W2T, C_HID, C_D);
    rowsq_kernel<<<M_BANK / 256, 256>>>(MBp, m2p);
    conv_half_kernel<<<(M_BANK * C_D / 4) / 1024, 256>>>(MBp, MB16);
    conv_half_kernel<<<(int)(((size_t)R_TOTAL * C_IN / 4) / 1024), 256>>>(features, X16);
    mlp_h<<<dim3(C_HID / 256, R_TOTAL / 128), 256, MLP_SMEM>>>(
        X16, W1T, b1, H16, C_IN, C_HID, 1);
    mlp_h<<<dim3(C_D / 256, R_TOTAL / 128), 256, MLP_SMEM>>>(
        H16, W2T, b2, P16, C_HID, C_D, 0);
    rowsq16_kernel<<<R_TOTAL / 256, 256>>>(P16, x2p);
    dist_tc<<<dim3(NSPLIT, R_TOTAL / 256), 512, DIST_SMEM>>>(P16, MB16);
    combine_kernel<<<R_TOTAL / 256, 256>>>(out);
}

// round 15
// speedup vs baseline: 1.2011x; 1.0703x over previous
#include <cuda_runtime.h>
#include <cuda_fp16.h>
#include <cstdint>

// ---------------------------------------------------------------------------
// PatchCoreAnomalyHead: all-fp16 mma.sync m16n8k16 (fp32 accumulate),
// ldmatrix fragment loads. x^2/m^2 from rounded halfs (fp16-consistent).
// (Resubmission of R14 — prior bench run failed with an infra error.)
// ---------------------------------------------------------------------------

#define R_TOTAL 32768
#define C_IN    1024
#define C_HID   512
#define C_D     256
#define M_BANK  16384
#define NSPLIT  8

__device__ __half g_X16[(size_t)R_TOTAL * C_IN];
__device__ __half g_H16[(size_t)R_TOTAL * C_HID];
__device__ __half g_P16[(size_t)R_TOTAL * C_D];
__device__ __half g_MB16[(size_t)M_BANK * C_D];
__device__ __half g_W1T[(size_t)C_HID * C_IN];
__device__ __half g_W2T[(size_t)C_D * C_HID];
__device__ float  g_m2[M_BANK];
__device__ float  g_x2[R_TOTAL];
__device__ float  g_pmin[NSPLIT * R_TOTAL];

// ---------------------------- helpers --------------------------------------
__device__ __forceinline__ uint32_t smem_u32(const void* p) {
    uint32_t a;
    asm("{ .reg .u64 t; cvta.to.shared.u64 t, %1; cvt.u32.u64 %0, t; }"
        : "=r"(a) : "l"(p));
    return a;
}
__device__ __forceinline__ void cp16(uint32_t dst, const void* src) {
    asm volatile("cp.async.cg.shared.global [%0], [%1], 16;" :: "r"(dst), "l"(src));
}
#define CP_COMMIT() asm volatile("cp.async.commit_group;" ::: "memory")
#define CP_WAIT0()  asm volatile("cp.async.wait_group 0;" ::: "memory")

__device__ __forceinline__ void ldsm4(uint32_t (&r)[4], uint32_t addr) {
    asm volatile("ldmatrix.sync.aligned.m8n8.x4.shared.b16 {%0,%1,%2,%3}, [%4];"
                 : "=r"(r[0]), "=r"(r[1]), "=r"(r[2]), "=r"(r[3]) : "r"(addr));
}
__device__ __forceinline__ void mma_f16(float (&d)[4],
                                        const uint32_t (&a)[4],
                                        uint32_t b0, uint32_t b1) {
    asm volatile(
        "mma.sync.aligned.m16n8k16.row.col.f32.f16.f16.f32 "
        "{%0,%1,%2,%3}, {%4,%5,%6,%7}, {%8,%9}, {%0,%1,%2,%3};"
        : "+f"(d[0]), "+f"(d[1]), "+f"(d[2]), "+f"(d[3])
        : "r"(a[0]), "r"(a[1]), "r"(a[2]), "r"(a[3]), "r"(b0), "r"(b1));
}

// fp16 k=64 slab, warp tile 64x64 (MLP), ldmatrix loads.
// aAddr: lane-resolved A base (row m0+(lane&15), k + (lane>>4)*8).
// bAddr: lane-resolved B base (n n0+(lane&7)+((lane>>4)&1)*8, k + ((lane>>3)&1)*8).
template <int ALD2, int BLD2>
__device__ __forceinline__ void compute_k64h64(uint32_t aAddr, uint32_t bAddr,
                                               float (&acc)[4][8][4]) {
#pragma unroll
    for (int s = 0; s < 4; s++) {
        uint32_t a[4][4], b4[4][4];
#pragma unroll
        for (int mi = 0; mi < 4; mi++)
            ldsm4(a[mi], aAddr + (uint32_t)(mi * 16 * ALD2) * 2 + s * 32);
#pragma unroll
        for (int p = 0; p < 4; p++)
            ldsm4(b4[p], bAddr + (uint32_t)(p * 16 * BLD2) * 2 + s * 32);
#pragma unroll
        for (int mi = 0; mi < 4; mi++)
#pragma unroll
            for (int p = 0; p < 4; p++) {
                mma_f16(acc[mi][2 * p],     a[mi], b4[p][0], b4[p][1]);
                mma_f16(acc[mi][2 * p + 1], a[mi], b4[p][2], b4[p][3]);
            }
    }
}

// fp16 k=64 slab, warp tile 64x32 (dist), ldmatrix loads.
template <int ALD2, int BLD2>
__device__ __forceinline__ void compute_k64h32(uint32_t aAddr, uint32_t bAddr,
                                               float (&acc)[4][4][4]) {
#pragma unroll
    for (int s = 0; s < 4; s++) {
        uint32_t a[4][4], b4[2][4];
#pragma unroll
        for (int mi = 0; mi < 4; mi++)
            ldsm4(a[mi], aAddr + (uint32_t)(mi * 16 * ALD2) * 2 + s * 32);
#pragma unroll
        for (int p = 0; p < 2; p++)
            ldsm4(b4[p], bAddr + (uint32_t)(p * 16 * BLD2) * 2 + s * 32);
#pragma unroll
        for (int mi = 0; mi < 4; mi++)
#pragma unroll
            for (int p = 0; p < 2; p++) {
                mma_f16(acc[mi][2 * p],     a[mi], b4[p][0], b4[p][1]);
                mma_f16(acc[mi][2 * p + 1], a[mi], b4[p][2], b4[p][3]);
            }
    }
}

// ------------------------- small prep kernels ------------------------------
__global__ void rowsq16_kernel(const __half* __restrict__ src, float* __restrict__ dst) {
    int i = blockIdx.x * blockDim.x + threadIdx.x;
    const __half2* p = (const __half2*)(src + (size_t)i * C_D);
    float s = 0.f;
#pragma unroll 16
    for (int q = 0; q < C_D / 2; q++) {
        float2 v = __half22float2(p[q]);
        s += v.x * v.x + v.y * v.y;
    }
    dst[i] = s;
}
__global__ void conv_half_kernel(const float* __restrict__ src, __half* __restrict__ dst) {
    int base = blockIdx.x * 1024 + threadIdx.x;
#pragma unroll
    for (int k = 0; k < 4; k++) {
        int i = base + k * 256;
        float4 v = ((const float4*)src)[i];
        __half2* d = (__half2*)(dst + (size_t)i * 4);
        d[0] = __floats2half2_rn(v.x, v.y);
        d[1] = __floats2half2_rn(v.z, v.w);
    }
}
__global__ void transpose32h(const float* __restrict__ src, __half* __restrict__ dst,
                             int R, int C) {
    __shared__ float tile[32][33];
    int bx = blockIdx.x * 32, by = blockIdx.y * 32;
    int tx = threadIdx.x & 31, ty = threadIdx.x >> 5;
#pragma unroll
    for (int i = 0; i < 32; i += 8)
        tile[ty + i][tx] = src[(size_t)(by + ty + i) * C + bx + tx];
    __syncthreads();
#pragma unroll
    for (int i = 0; i < 32; i += 8)
        dst[(size_t)(bx + ty + i) * R + by + tx] = __float2half(tile[tx][ty + i]);
}

// ----------- MLP GEMM (fp16): Y16 = act(X16 @ WT16^T + bias) ---------------
#define MLDK    136                               // halfs; 136/2 ≡ 4 mod 32
#define MA_SZ   (128 * MLDK * 2)
#define MB_SZ   (256 * MLDK * 2)
#define MLP_SMEM (2 * (MA_SZ + MB_SZ))            // 208896

__global__ void __launch_bounds__(256)
mlp_h(const __half* __restrict__ X, const __half* __restrict__ WT,
      const float* __restrict__ bias, __half* __restrict__ Y16,
      int K, int N, int relu) {
    extern __shared__ char sm[];
    const uint32_t sbase = smem_u32(sm);
    const uint32_t Aoff[2] = {0u, MA_SZ};
    const uint32_t Boff[2] = {2 * MA_SZ, 2 * MA_SZ + MB_SZ};

    const int t = threadIdx.x, w = t >> 5, lane = t & 31;
    const int q = lane >> 2, c = lane & 3;
    const int wr = w & 1, wc = w >> 1;
    const int row0 = blockIdx.y * 128, col0 = blockIdx.x * 256;
    const int cr = t >> 4, seg = (t & 15) * 16;

    // ldmatrix lane bases (byte offsets within tile)
    const uint32_t aLane = (uint32_t)(((wr * 64) + (lane & 15)) * MLDK
                                      + ((lane >> 4) << 3)) * 2;
    const uint32_t bLane = (uint32_t)(((wc * 64) + (lane & 7) + ((lane >> 4) & 1) * 8)
                                      * MLDK + (((lane >> 3) & 1) << 3)) * 2;

    float acc[4][8][4];
#pragma unroll
    for (int mi = 0; mi < 4; mi++)
#pragma unroll
        for (int ni = 0; ni < 8; ni++)
#pragma unroll
            for (int e = 0; e < 4; e++) acc[mi][ni][e] = 0.f;

    auto copy_chunk = [&](int j, int buf) {
#pragma unroll
        for (int i = 0; i < 8; i++) {
            int rr = cr + i * 16;
            cp16(sbase + Aoff[buf] + (uint32_t)(rr * MLDK) * 2 + seg,
                 (const char*)(X + (size_t)(row0 + rr) * K + j * 128) + seg);
        }
#pragma unroll
        for (int i = 0; i < 16; i++) {
            int rr = cr + i * 16;
            cp16(sbase + Boff[buf] + (uint32_t)(rr * MLDK) * 2 + seg,
                 (const char*)(WT + (size_t)(col0 + rr) * K + j * 128) + seg);
        }
    };

    const int nch = K / 128;
    copy_chunk(0, 0);
    CP_COMMIT();
    for (int j = 0; j < nch; j++) {
        CP_WAIT0();
        __syncthreads();
        if (j + 1 < nch) { copy_chunk(j + 1, (j + 1) & 1); CP_COMMIT(); }
        uint32_t aA = sbase + Aoff[j & 1] + aLane;
        uint32_t bA = sbase + Boff[j & 1] + bLane;
        compute_k64h64<MLDK, MLDK>(aA, bA, acc);
        compute_k64h64<MLDK, MLDK>(aA + 128, bA + 128, acc);
    }

#pragma unroll
    for (int mi = 0; mi < 4; mi++) {
        int rg = row0 + wr * 64 + mi * 16 + q;
#pragma unroll
        for (int ni = 0; ni < 8; ni++) {
            int cg = col0 + wc * 64 + ni * 8 + 2 * c;
            float2 bv = *(const float2*)(bias + cg);
            float v0 = acc[mi][ni][0] + bv.x;
            float v1 = acc[mi][ni][1] + bv.y;
            float v2 = acc[mi][ni][2] + bv.x;
            float v3 = acc[mi][ni][3] + bv.y;
            if (relu) {
                v0 = fmaxf(v0, 0.f); v1 = fmaxf(v1, 0.f);
                v2 = fmaxf(v2, 0.f); v3 = fmaxf(v3, 0.f);
            }
            *(__half2*)&Y16[(size_t)rg * N + cg] = __floats2half2_rn(v0, v1);
            *(__half2*)&Y16[(size_t)(rg + 8) * N + cg] = __floats2half2_rn(v2, v3);
        }
    }
}

// ---------------- fused distance + partial min (fp16, 512 thr) -------------
#define ALD2    264                                // halfs; 264/2 ≡ 4 mod 32
#define BLDD    136                                // halfs; 136/2 ≡ 4 mod 32
#define AH_SZ   (256 * ALD2 * 2)                   // 135168
#define BH_SZ   (128 * BLDD * 2)                   // 34816
#define RED_OFF (AH_SZ + 2 * BH_SZ)                // 204800
#define DIST_SMEM (RED_OFF + 4 * 256 * 4)          // 208896

__global__ void __launch_bounds__(512)
dist_tc(const __half* __restrict__ P16, const __half* __restrict__ MB16) {
    extern __shared__ char sm[];
    const uint32_t sbase = smem_u32(sm);
    const uint32_t Boff[2] = {AH_SZ, AH_SZ + BH_SZ};
    float* red = (float*)(sm + RED_OFF);

    const int t = threadIdx.x, w = t >> 5, lane = t & 31;
    const int q = lane >> 2, c = lane & 3;
    const int wr = w & 3, wc = w >> 2;
    const int row0 = blockIdx.y * 256;
    const int qbase = blockIdx.x * (M_BANK / NSPLIT);

    // stationary P16 tile: 256 rows x 256 halfs
#pragma unroll
    for (int i = 0; i < 16; i++) {
        int f = t + i * 512;
        int rr = f >> 5, seg = f & 31;
        cp16(sbase + (uint32_t)(rr * ALD2 + seg * 8) * 2,
             P16 + (size_t)(row0 + rr) * C_D + seg * 8);
    }

    auto copy_chunk = [&](int jj, int buf) {
        int nt = jj >> 1, kc = jj & 1;
        int rr = t >> 2, sq = (t & 3) * 64;
        const char* src = (const char*)(MB16 + (size_t)(qbase + nt * 128 + rr) * C_D
                                        + kc * 128) + sq;
        uint32_t dst = sbase + Boff[buf] + (uint32_t)(rr * BLDD) * 2 + sq;
        cp16(dst, src);
        cp16(dst + 16, src + 16);
        cp16(dst + 32, src + 32);
        cp16(dst + 48, src + 48);
    };

    // ldmatrix lane bases
    const uint32_t aLane = sbase + (uint32_t)(((wr * 64) + (lane & 15)) * ALD2
                                              + ((lane >> 4) << 3)) * 2;
    const uint32_t bLane = (uint32_t)(((wc * 32) + (lane & 7) + ((lane >> 4) & 1) * 8)
                                      * BLDD + (((lane >> 3) & 1) << 3)) * 2;

    float acc[4][4][4];
#pragma unroll
    for (int mi = 0; mi < 4; mi++)
#pragma unroll
        for (int ni = 0; ni < 4; ni++)
#pragma unroll
            for (int e = 0; e < 4; e++) acc[mi][ni][e] = 0.f;
    float runmin[4][2];
#pragma unroll
    for (int mi = 0; mi < 4; mi++) { runmin[mi][0] = 3.402823e38f; runmin[mi][1] = 3.402823e38f; }

    copy_chunk(0, 0);
    CP_COMMIT();
    const int NCH = (M_BANK / NSPLIT / 128) * 2;   // 32 chunks (k128 each)
    for (int jj = 0; jj < NCH; jj++) {
        CP_WAIT0();
        __syncthreads();                            // covers As (jj=0) + reuse
        if (jj + 1 < NCH) { copy_chunk(jj + 1, (jj + 1) & 1); CP_COMMIT(); }
        const int kc = jj & 1;
        uint32_t aA = aLane + kc * 256;
        uint32_t bA = sbase + Boff[jj & 1] + bLane;
        compute_k64h32<ALD2, BLDD>(aA, bA, acc);
        compute_k64h32<ALD2, BLDD>(aA + 128, bA + 128, acc);
        if (kc == 1) {
            const int nt = jj >> 1;
            const float* m2p = g_m2 + qbase + nt * 128 + wc * 32 + 2 * c;
#pragma unroll
            for (int mi = 0; mi < 4; mi++) {
                float m0 = runmin[mi][0], m1 = runmin[mi][1];
#pragma unroll
                for (int ni = 0; ni < 4; ni++) {
                    float2 m2v = *(const float2*)(m2p + ni * 8);
                    m0 = fminf(m0, fmaf(-2.f, acc[mi][ni][0], m2v.x));
                    m0 = fminf(m0, fmaf(-2.f, acc[mi][ni][1], m2v.y));
                    m1 = fminf(m1, fmaf(-2.f, acc[mi][ni][2], m2v.x));
                    m1 = fminf(m1, fmaf(-2.f, acc[mi][ni][3], m2v.y));
                    acc[mi][ni][0] = 0.f; acc[mi][ni][1] = 0.f;
                    acc[mi][ni][2] = 0.f; acc[mi][ni][3] = 0.f;
                }
                runmin[mi][0] = m0; runmin[mi][1] = m1;
            }
        }
    }

#pragma unroll
    for (int mi = 0; mi < 4; mi++)
#pragma unroll
        for (int s = 0; s < 2; s++) {
            float v = runmin[mi][s];
            v = fminf(v, __shfl_xor_sync(0xffffffffu, v, 1));
            v = fminf(v, __shfl_xor_sync(0xffffffffu, v, 2));
            if (c == 0) red[wc * 256 + wr * 64 + mi * 16 + s * 8 + q] = v;
        }
    __syncthreads();
    if (t < 256) {
        float m = fminf(fminf(red[t], red[256 + t]),
                        fminf(red[512 + t], red[768 + t]));
        g_pmin[(size_t)blockIdx.x * R_TOTAL + row0 + t] = m;
    }
}

// ------------------------------ combine ------------------------------------
__global__ void combine_kernel(float* __restrict__ out) {
    int r = blockIdx.x * blockDim.x + threadIdx.x;
    float m = 3.402823e38f;
#pragma unroll
    for (int s = 0; s < NSPLIT; s++)
        m = fminf(m, g_pmin[(size_t)s * R_TOTAL + r]);
    out[r] = sqrtf(fmaxf(g_x2[r] + m, 0.f));
}

// ---------------------------------------------------------------------------
extern "C" void kernel_launch(void* const* d_in, const int* in_sizes, int n_in,
                              void* d_out, int out_size) {
    (void)in_sizes; (void)n_in; (void)out_size;
    const float* features = (const float*)d_in[0];
    const float* W1       = (const float*)d_in[1];
    const float* b1       = (const float*)d_in[2];
    const float* W2       = (const float*)d_in[3];
    const float* b2       = (const float*)d_in[4];
    const float* MBp      = (const float*)d_in[5];
    float* out            = (float*)d_out;

    float *m2p, *x2p;
    __half *X16, *H16, *P16, *MB16, *W1T, *W2T;
    cudaGetSymbolAddress((void**)&X16, g_X16);
    cudaGetSymbolAddress((void**)&H16, g_H16);
    cudaGetSymbolAddress((void**)&P16, g_P16);
    cudaGetSymbolAddress((void**)&MB16, g_MB16);
    cudaGetSymbolAddress((void**)&W1T, g_W1T);
    cudaGetSymbolAddress((void**)&W2T, g_W2T);
    cudaGetSymbolAddress((void**)&m2p, g_m2);
    cudaGetSymbolAddress((void**)&x2p, g_x2);

    cudaFuncSetAttribute(mlp_h, cudaFuncAttributeMaxDynamicSharedMemorySize, MLP_SMEM);
    cudaFuncSetAttribute(dist_tc, cudaFuncAttributeMaxDynamicSharedMemorySize, DIST_SMEM);

    transpose32h<<<dim3(C_HID / 32, C_IN / 32), 256>>>(W1, W1T, C_IN, C_HID);
    transpose32h<<<dim3(C_D / 32, C_HID / 32), 256>>>(W2, W2T, C_HID, C_D);
    conv_half_kernel<<<(M_BANK * C_D / 4) / 1024, 256>>>(MBp, MB16);
    rowsq16_kernel<<<M_BANK / 256, 256>>>(MB16, m2p);      // m2 from rounded halfs
    conv_half_kernel<<<(int)(((size_t)R_TOTAL * C_IN / 4) / 1024), 256>>>(features, X16);
    mlp_h<<<dim3(C_HID / 256, R_TOTAL / 128), 256, MLP_SMEM>>>(
        X16, W1T, b1, H16, C_IN, C_HID, 1);
    mlp_h<<<dim3(C_D / 256, R_TOTAL / 128), 256, MLP_SMEM>>>(
        H16, W2T, b2, P16, C_HID, C_D, 0);
    rowsq16_kernel<<<R_TOTAL / 256, 256>>>(P16, x2p);
    dist_tc<<<dim3(NSPLIT, R_TOTAL / 256), 512, DIST_SMEM>>>(P16, MB16);
    combine_kernel<<<R_TOTAL / 256, 256>>>(out);
}

// round 16
// speedup vs baseline: 1.2264x; 1.0211x over previous
#include <cuda_runtime.h>
#include <cuda_fp16.h>
#include <cstdint>

// ---------------------------------------------------------------------------
// PatchCoreAnomalyHead: fp16 mma.sync m16n8k16 + ldmatrix.
// MLP: fp32 accumulate. Dist: fp16 accumulate (16 chained k16 roundings,
// |err| ~0.03 on dot -> dist rel_err ~1e-4, 10x under threshold).
// x^2/m^2 from rounded halfs (fp16-consistent algebra).
// ---------------------------------------------------------------------------

#define R_TOTAL 32768
#define C_IN    1024
#define C_HID   512
#define C_D     256
#define M_BANK  16384
#define NSPLIT  8

__device__ __half g_X16[(size_t)R_TOTAL * C_IN];
__device__ __half g_H16[(size_t)R_TOTAL * C_HID];
__device__ __half g_P16[(size_t)R_TOTAL * C_D];
__device__ __half g_MB16[(size_t)M_BANK * C_D];
__device__ __half g_W1T[(size_t)C_HID * C_IN];
__device__ __half g_W2T[(size_t)C_D * C_HID];
__device__ float  g_m2[M_BANK];
__device__ float  g_x2[R_TOTAL];
__device__ float  g_pmin[NSPLIT * R_TOTAL];

// ---------------------------- helpers --------------------------------------
__device__ __forceinline__ uint32_t smem_u32(const void* p) {
    uint32_t a;
    asm("{ .reg .u64 t; cvta.to.shared.u64 t, %1; cvt.u32.u64 %0, t; }"
        : "=r"(a) : "l"(p));
    return a;
}
__device__ __forceinline__ void cp16(uint32_t dst, const void* src) {
    asm volatile("cp.async.cg.shared.global [%0], [%1], 16;" :: "r"(dst), "l"(src));
}
#define CP_COMMIT() asm volatile("cp.async.commit_group;" ::: "memory")
#define CP_WAIT0()  asm volatile("cp.async.wait_group 0;" ::: "memory")

__device__ __forceinline__ void ldsm4(uint32_t (&r)[4], uint32_t addr) {
    asm volatile("ldmatrix.sync.aligned.m8n8.x4.shared.b16 {%0,%1,%2,%3}, [%4];"
                 : "=r"(r[0]), "=r"(r[1]), "=r"(r[2]), "=r"(r[3]) : "r"(addr));
}
__device__ __forceinline__ void mma_f16(float (&d)[4],
                                        const uint32_t (&a)[4],
                                        uint32_t b0, uint32_t b1) {
    asm volatile(
        "mma.sync.aligned.m16n8k16.row.col.f32.f16.f16.f32 "
        "{%0,%1,%2,%3}, {%4,%5,%6,%7}, {%8,%9}, {%0,%1,%2,%3};"
        : "+f"(d[0]), "+f"(d[1]), "+f"(d[2]), "+f"(d[3])
        : "r"(a[0]), "r"(a[1]), "r"(a[2]), "r"(a[3]), "r"(b0), "r"(b1));
}
// fp16-accumulate variant: d = {c0c1, c2c3} packed half2s
__device__ __forceinline__ void mma_h16(uint32_t (&d)[2],
                                        const uint32_t (&a)[4],
                                        uint32_t b0, uint32_t b1) {
    asm volatile(
        "mma.sync.aligned.m16n8k16.row.col.f16.f16.f16.f16 "
        "{%0,%1}, {%2,%3,%4,%5}, {%6,%7}, {%0,%1};"
        : "+r"(d[0]), "+r"(d[1])
        : "r"(a[0]), "r"(a[1]), "r"(a[2]), "r"(a[3]), "r"(b0), "r"(b1));
}

// fp16 k=64 slab, warp tile 64x64 (MLP), ldmatrix, fp32 acc.
template <int ALD2, int BLD2>
__device__ __forceinline__ void compute_k64h64(uint32_t aAddr, uint32_t bAddr,
                                               float (&acc)[4][8][4]) {
#pragma unroll
    for (int s = 0; s < 4; s++) {
        uint32_t a[4][4], b4[4][4];
#pragma unroll
        for (int mi = 0; mi < 4; mi++)
            ldsm4(a[mi], aAddr + (uint32_t)(mi * 16 * ALD2) * 2 + s * 32);
#pragma unroll
        for (int p = 0; p < 4; p++)
            ldsm4(b4[p], bAddr + (uint32_t)(p * 16 * BLD2) * 2 + s * 32);
#pragma unroll
        for (int mi = 0; mi < 4; mi++)
#pragma unroll
            for (int p = 0; p < 4; p++) {
                mma_f16(acc[mi][2 * p],     a[mi], b4[p][0], b4[p][1]);
                mma_f16(acc[mi][2 * p + 1], a[mi], b4[p][2], b4[p][3]);
            }
    }
}

// fp16 k=64 slab, warp tile 64x32 (dist), ldmatrix, fp16 acc.
template <int ALD2, int BLD2>
__device__ __forceinline__ void compute_k64h32(uint32_t aAddr, uint32_t bAddr,
                                               uint32_t (&acc)[4][4][2]) {
#pragma unroll
    for (int s = 0; s < 4; s++) {
        uint32_t a[4][4], b4[2][4];
#pragma unroll
        for (int mi = 0; mi < 4; mi++)
            ldsm4(a[mi], aAddr + (uint32_t)(mi * 16 * ALD2) * 2 + s * 32);
#pragma unroll
        for (int p = 0; p < 2; p++)
            ldsm4(b4[p], bAddr + (uint32_t)(p * 16 * BLD2) * 2 + s * 32);
#pragma unroll
        for (int mi = 0; mi < 4; mi++)
#pragma unroll
            for (int p = 0; p < 2; p++) {
                mma_h16(acc[mi][2 * p],     a[mi], b4[p][0], b4[p][1]);
                mma_h16(acc[mi][2 * p + 1], a[mi], b4[p][2], b4[p][3]);
            }
    }
}

// ------------------------- small prep kernels ------------------------------
// 8 threads per row, shfl reduce. rows*8 must be divisible by 256.
__global__ void rowsq16_kernel(const __half* __restrict__ src, float* __restrict__ dst,
                               int ncols_half2) {
    int gid = blockIdx.x * blockDim.x + threadIdx.x;
    int row = gid >> 3, sl = gid & 7;
    const __half2* p = (const __half2*)src + (size_t)row * ncols_half2 + sl * (ncols_half2 >> 3);
    float s = 0.f;
#pragma unroll 16
    for (int q = 0; q < 16; q++) {              // 16 half2 per slice (C_D=256)
        float2 v = __half22float2(p[q]);
        s += v.x * v.x + v.y * v.y;
    }
    s += __shfl_xor_sync(0xffffffffu, s, 1);
    s += __shfl_xor_sync(0xffffffffu, s, 2);
    s += __shfl_xor_sync(0xffffffffu, s, 4);
    if (sl == 0) dst[row] = s;
}
__global__ void conv_half_kernel(const float* __restrict__ src, __half* __restrict__ dst) {
    int base = blockIdx.x * 1024 + threadIdx.x;
#pragma unroll
    for (int k = 0; k < 4; k++) {
        int i = base + k * 256;
        float4 v = ((const float4*)src)[i];
        __half2* d = (__half2*)(dst + (size_t)i * 4);
        d[0] = __floats2half2_rn(v.x, v.y);
        d[1] = __floats2half2_rn(v.z, v.w);
    }
}
__global__ void transpose32h(const float* __restrict__ src, __half* __restrict__ dst,
                             int R, int C) {
    __shared__ float tile[32][33];
    int bx = blockIdx.x * 32, by = blockIdx.y * 32;
    int tx = threadIdx.x & 31, ty = threadIdx.x >> 5;
#pragma unroll
    for (int i = 0; i < 32; i += 8)
        tile[ty + i][tx] = src[(size_t)(by + ty + i) * C + bx + tx];
    __syncthreads();
#pragma unroll
    for (int i = 0; i < 32; i += 8)
        dst[(size_t)(bx + ty + i) * R + by + tx] = __float2half(tile[tx][ty + i]);
}

// ----------- MLP GEMM (fp16): Y16 = act(X16 @ WT16^T + bias) ---------------
#define MLDK    136                               // halfs; 136/2 ≡ 4 mod 32
#define MA_SZ   (128 * MLDK * 2)
#define MB_SZ   (256 * MLDK * 2)
#define MLP_SMEM (2 * (MA_SZ + MB_SZ))            // 208896

__global__ void __launch_bounds__(256)
mlp_h(const __half* __restrict__ X, const __half* __restrict__ WT,
      const float* __restrict__ bias, __half* __restrict__ Y16,
      int K, int N, int relu) {
    extern __shared__ char sm[];
    const uint32_t sbase = smem_u32(sm);
    const uint32_t Aoff[2] = {0u, MA_SZ};
    const uint32_t Boff[2] = {2 * MA_SZ, 2 * MA_SZ + MB_SZ};

    const int t = threadIdx.x, w = t >> 5, lane = t & 31;
    const int q = lane >> 2, c = lane & 3;
    const int wr = w & 1, wc = w >> 1;
    const int row0 = blockIdx.y * 128, col0 = blockIdx.x * 256;
    const int cr = t >> 4, seg = (t & 15) * 16;

    const uint32_t aLane = (uint32_t)(((wr * 64) + (lane & 15)) * MLDK
                                      + ((lane >> 4) << 3)) * 2;
    const uint32_t bLane = (uint32_t)(((wc * 64) + (lane & 7) + ((lane >> 4) & 1) * 8)
                                      * MLDK + (((lane >> 3) & 1) << 3)) * 2;

    float acc[4][8][4];
#pragma unroll
    for (int mi = 0; mi < 4; mi++)
#pragma unroll
        for (int ni = 0; ni < 8; ni++)
#pragma unroll
            for (int e = 0; e < 4; e++) acc[mi][ni][e] = 0.f;

    auto copy_chunk = [&](int j, int buf) {
#pragma unroll
        for (int i = 0; i < 8; i++) {
            int rr = cr + i * 16;
            cp16(sbase + Aoff[buf] + (uint32_t)(rr * MLDK) * 2 + seg,
                 (const char*)(X + (size_t)(row0 + rr) * K + j * 128) + seg);
        }
#pragma unroll
        for (int i = 0; i < 16; i++) {
            int rr = cr + i * 16;
            cp16(sbase + Boff[buf] + (uint32_t)(rr * MLDK) * 2 + seg,
                 (const char*)(WT + (size_t)(col0 + rr) * K + j * 128) + seg);
        }
    };

    const int nch = K / 128;
    copy_chunk(0, 0);
    CP_COMMIT();
    for (int j = 0; j < nch; j++) {
        CP_WAIT0();
        __syncthreads();
        if (j + 1 < nch) { copy_chunk(j + 1, (j + 1) & 1); CP_COMMIT(); }
        uint32_t aA = sbase + Aoff[j & 1] + aLane;
        uint32_t bA = sbase + Boff[j & 1] + bLane;
        compute_k64h64<MLDK, MLDK>(aA, bA, acc);
        compute_k64h64<MLDK, MLDK>(aA + 128, bA + 128, acc);
    }

#pragma unroll
    for (int mi = 0; mi < 4; mi++) {
        int rg = row0 + wr * 64 + mi * 16 + q;
#pragma unroll
        for (int ni = 0; ni < 8; ni++) {
            int cg = col0 + wc * 64 + ni * 8 + 2 * c;
            float2 bv = *(const float2*)(bias + cg);
            float v0 = acc[mi][ni][0] + bv.x;
            float v1 = acc[mi][ni][1] + bv.y;
            float v2 = acc[mi][ni][2] + bv.x;
            float v3 = acc[mi][ni][3] + bv.y;
            if (relu) {
                v0 = fmaxf(v0, 0.f); v1 = fmaxf(v1, 0.f);
                v2 = fmaxf(v2, 0.f); v3 = fmaxf(v3, 0.f);
            }
            *(__half2*)&Y16[(size_t)rg * N + cg] = __floats2half2_rn(v0, v1);
            *(__half2*)&Y16[(size_t)(rg + 8) * N + cg] = __floats2half2_rn(v2, v3);
        }
    }
}

// ---------------- fused distance + partial min (fp16 acc) ------------------
#define ALD2    264                                // halfs; 264/2 ≡ 4 mod 32
#define BLDD    136                                // halfs; 136/2 ≡ 4 mod 32
#define AH_SZ   (256 * ALD2 * 2)                   // 135168
#define BH_SZ   (128 * BLDD * 2)                   // 34816
#define RED_OFF (AH_SZ + 2 * BH_SZ)                // 204800
#define DIST_SMEM (RED_OFF + 4 * 256 * 4)          // 208896

__global__ void __launch_bounds__(512)
dist_tc(const __half* __restrict__ P16, const __half* __restrict__ MB16) {
    extern __shared__ char sm[];
    const uint32_t sbase = smem_u32(sm);
    const uint32_t Boff[2] = {AH_SZ, AH_SZ + BH_SZ};
    float* red = (float*)(sm + RED_OFF);

    const int t = threadIdx.x, w = t >> 5, lane = t & 31;
    const int q = lane >> 2, c = lane & 3;
    const int wr = w & 3, wc = w >> 2;
    const int row0 = blockIdx.y * 256;
    const int qbase = blockIdx.x * (M_BANK / NSPLIT);

    // stationary P16 tile: 256 rows x 256 halfs
#pragma unroll
    for (int i = 0; i < 16; i++) {
        int f = t + i * 512;
        int rr = f >> 5, seg = f & 31;
        cp16(sbase + (uint32_t)(rr * ALD2 + seg * 8) * 2,
             P16 + (size_t)(row0 + rr) * C_D + seg * 8);
    }

    auto copy_chunk = [&](int jj, int buf) {
        int nt = jj >> 1, kc = jj & 1;
        int rr = t >> 2, sq = (t & 3) * 64;
        const char* src = (const char*)(MB16 + (size_t)(qbase + nt * 128 + rr) * C_D
                                        + kc * 128) + sq;
        uint32_t dst = sbase + Boff[buf] + (uint32_t)(rr * BLDD) * 2 + sq;
        cp16(dst, src);
        cp16(dst + 16, src + 16);
        cp16(dst + 32, src + 32);
        cp16(dst + 48, src + 48);
    };

    const uint32_t aLane = sbase + (uint32_t)(((wr * 64) + (lane & 15)) * ALD2
                                              + ((lane >> 4) << 3)) * 2;
    const uint32_t bLane = (uint32_t)(((wc * 32) + (lane & 7) + ((lane >> 4) & 1) * 8)
                                      * BLDD + (((lane >> 3) & 1) << 3)) * 2;

    uint32_t acc[4][4][2];
#pragma unroll
    for (int mi = 0; mi < 4; mi++)
#pragma unroll
        for (int ni = 0; ni < 4; ni++) { acc[mi][ni][0] = 0u; acc[mi][ni][1] = 0u; }
    float runmin[4][2];
#pragma unroll
    for (int mi = 0; mi < 4; mi++) { runmin[mi][0] = 3.402823e38f; runmin[mi][1] = 3.402823e38f; }

    copy_chunk(0, 0);
    CP_COMMIT();
    const int NCH = (M_BANK / NSPLIT / 128) * 2;   // 32 chunks (k128 each)
    for (int jj = 0; jj < NCH; jj++) {
        CP_WAIT0();
        __syncthreads();                            // covers As (jj=0) + reuse
        if (jj + 1 < NCH) { copy_chunk(jj + 1, (jj + 1) & 1); CP_COMMIT(); }
        const int kc = jj & 1;
        uint32_t aA = aLane + kc * 256;
        uint32_t bA = sbase + Boff[jj & 1] + bLane;
        compute_k64h32<ALD2, BLDD>(aA, bA, acc);
        compute_k64h32<ALD2, BLDD>(aA + 128, bA + 128, acc);
        if (kc == 1) {
            const int nt = jj >> 1;
            const float* m2p = g_m2 + qbase + nt * 128 + wc * 32 + 2 * c;
#pragma unroll
            for (int mi = 0; mi < 4; mi++) {
                float m0 = runmin[mi][0], m1 = runmin[mi][1];
#pragma unroll
                for (int ni = 0; ni < 4; ni++) {
                    float2 m2v = *(const float2*)(m2p + ni * 8);
                    float2 lo = __half22float2(*(__half2*)&acc[mi][ni][0]);
                    float2 hi = __half22float2(*(__half2*)&acc[mi][ni][1]);
                    m0 = fminf(m0, fmaf(-2.f, lo.x, m2v.x));
                    m0 = fminf(m0, fmaf(-2.f, lo.y, m2v.y));
                    m1 = fminf(m1, fmaf(-2.f, hi.x, m2v.x));
                    m1 = fminf(m1, fmaf(-2.f, hi.y, m2v.y));
                    acc[mi][ni][0] = 0u; acc[mi][ni][1] = 0u;
                }
                runmin[mi][0] = m0; runmin[mi][1] = m1;
            }
        }
    }

#pragma unroll
    for (int mi = 0; mi < 4; mi++)
#pragma unroll
        for (int s = 0; s < 2; s++) {
            float v = runmin[mi][s];
            v = fminf(v, __shfl_xor_sync(0xffffffffu, v, 1));
            v = fminf(v, __shfl_xor_sync(0xffffffffu, v, 2));
            if (c == 0) red[wc * 256 + wr * 64 + mi * 16 + s * 8 + q] = v;
        }
    __syncthreads();
    if (t < 256) {
        float m = fminf(fminf(red[t], red[256 + t]),
                        fminf(red[512 + t], red[768 + t]));
        g_pmin[(size_t)blockIdx.x * R_TOTAL + row0 + t] = m;
    }
}

// ------------------------------ combine ------------------------------------
__global__ void combine_kernel(float* __restrict__ out) {
    int r = blockIdx.x * blockDim.x + threadIdx.x;
    float m = 3.402823e38f;
#pragma unroll
    for (int s = 0; s < NSPLIT; s++)
        m = fminf(m, g_pmin[(size_t)s * R_TOTAL + r]);
    out[r] = sqrtf(fmaxf(g_x2[r] + m, 0.f));
}

// ---------------------------------------------------------------------------
extern "C" void kernel_launch(void* const* d_in, const int* in_sizes, int n_in,
                              void* d_out, int out_size) {
    (void)in_sizes; (void)n_in; (void)out_size;
    const float* features = (const float*)d_in[0];
    const float* W1       = (const float*)d_in[1];
    const float* b1       = (const float*)d_in[2];
    const float* W2       = (const float*)d_in[3];
    const float* b2       = (const float*)d_in[4];
    const float* MBp      = (const float*)d_in[5];
    float* out            = (float*)d_out;

    float *m2p, *x2p;
    __half *X16, *H16, *P16, *MB16, *W1T, *W2T;
    cudaGetSymbolAddress((void**)&X16, g_X16);
    cudaGetSymbolAddress((void**)&H16, g_H16);
    cudaGetSymbolAddress((void**)&P16, g_P16);
    cudaGetSymbolAddress((void**)&MB16, g_MB16);
    cudaGetSymbolAddress((void**)&W1T, g_W1T);
    cudaGetSymbolAddress((void**)&W2T, g_W2T);
    cudaGetSymbolAddress((void**)&m2p, g_m2);
    cudaGetSymbolAddress((void**)&x2p, g_x2);

    cudaFuncSetAttribute(mlp_h, cudaFuncAttributeMaxDynamicSharedMemorySize, MLP_SMEM);
    cudaFuncSetAttribute(dist_tc, cudaFuncAttributeMaxDynamicSharedMemorySize, DIST_SMEM);

    transpose32h<<<dim3(C_HID / 32, C_IN / 32), 256>>>(W1, W1T, C_IN, C_HID);
    transpose32h<<<dim3(C_D / 32, C_HID / 32), 256>>>(W2, W2T, C_HID, C_D);
    conv_half_kernel<<<(M_BANK * C_D / 4) / 1024, 256>>>(MBp, MB16);
    rowsq16_kernel<<<M_BANK * 8 / 256, 256>>>(MB16, m2p, C_D / 2);
    conv_half_kernel<<<(int)(((size_t)R_TOTAL * C_IN / 4) / 1024), 256>>>(features, X16);
    mlp_h<<<dim3(C_HID / 256, R_TOTAL / 128), 256, MLP_SMEM>>>(
        X16, W1T, b1, H16, C_IN, C_HID, 1);
    mlp_h<<<dim3(C_D / 256, R_TOTAL / 128), 256, MLP_SMEM>>>(
        H16, W2T, b2, P16, C_HID, C_D, 0);
    rowsq16_kernel<<<R_TOTAL * 8 / 256, 256>>>(P16, x2p, C_D / 2);
    dist_tc<<<dim3(NSPLIT, R_TOTAL / 256), 512, DIST_SMEM>>>(P16, MB16);
    combine_kernel<<<R_TOTAL / 256, 256>>>(out);
}